// round 1
// baseline (speedup 1.0000x reference)
#include <cuda_runtime.h>
#include <cstddef>

#define NN 100000
#define DD 128
#define EMAX 1600000

// ---- static device scratch (no allocations allowed) ----
__device__ int   g_count[NN];
__device__ int   g_offsets[NN + 1];
__device__ int   g_cursor[NN];
__device__ int   g_sorted[EMAX];
__device__ float g_mean[(size_t)NN * DD];
__device__ float g_h1[(size_t)NN * DD];
__device__ float g_h2[(size_t)NN * DD];
__device__ float g_bt1[256 * 128];   // [k][j]: k<128 -> Wl[j][k], k>=128 -> Wr[j][k-128]
__device__ float g_bt2[256 * 128];

// ---------------------------------------------------------------------------
__global__ void zero_count_kernel() {
    int i = blockIdx.x * blockDim.x + threadIdx.x;
    if (i < NN) g_count[i] = 0;
}

__global__ void hist_kernel(const int* __restrict__ dst, int E) {
    for (int e = blockIdx.x * blockDim.x + threadIdx.x; e < E; e += gridDim.x * blockDim.x)
        atomicAdd(&g_count[dst[e]], 1);
}

// single-block sequential-chunk scan over NN counters -> exclusive offsets + cursor
__global__ void scan_kernel() {
    __shared__ int warp_sums[32];
    int lane = threadIdx.x & 31, wid = threadIdx.x >> 5;
    int carry = 0;
    for (int base = 0; base < NN; base += 1024) {
        int i = base + threadIdx.x;
        int v = (i < NN) ? g_count[i] : 0;
        int x = v;
        #pragma unroll
        for (int o = 1; o < 32; o <<= 1) {
            int y = __shfl_up_sync(0xffffffffu, x, o);
            if (lane >= o) x += y;
        }
        if (lane == 31) warp_sums[wid] = x;
        __syncthreads();
        if (wid == 0) {
            int s = warp_sums[lane];
            #pragma unroll
            for (int o = 1; o < 32; o <<= 1) {
                int y = __shfl_up_sync(0xffffffffu, s, o);
                if (lane >= o) s += y;
            }
            warp_sums[lane] = s;
        }
        __syncthreads();
        int woff = wid ? warp_sums[wid - 1] : 0;
        int excl = carry + woff + x - v;
        if (i < NN) { g_offsets[i] = excl; g_cursor[i] = excl; }
        int total = warp_sums[31];
        __syncthreads();
        carry += total;
    }
    if (threadIdx.x == 0) g_offsets[NN] = carry;
}

__global__ void scatter_kernel(const int* __restrict__ src, const int* __restrict__ dst, int E) {
    for (int e = blockIdx.x * blockDim.x + threadIdx.x; e < E; e += gridDim.x * blockDim.x) {
        int d = dst[e];
        int pos = atomicAdd(&g_cursor[d], 1);
        g_sorted[pos] = src[e];
    }
}

// pack [Wl;Wr] (each [j=128][k=128] row-major) into BT[k=256][j=128]
__global__ void pack_bt_kernel(const float* __restrict__ wl, const float* __restrict__ wr,
                               float* __restrict__ bt) {
    int idx = blockIdx.x * blockDim.x + threadIdx.x;
    if (idx >= 256 * 128) return;
    int k = idx >> 7, j = idx & 127;
    bt[idx] = (k < 128) ? wl[j * 128 + k] : wr[j * 128 + (k - 128)];
}

// pull-based mean aggregation: one warp per dst node, float4 per lane
__global__ void agg_kernel(const float4* __restrict__ x4, float4* __restrict__ out4) {
    int gw = (blockIdx.x * blockDim.x + threadIdx.x) >> 5;
    int lane = threadIdx.x & 31;
    if (gw >= NN) return;
    int beg = g_offsets[gw], end = g_offsets[gw + 1];
    float4 acc = make_float4(0.f, 0.f, 0.f, 0.f);
    for (int p = beg; p < end; p++) {
        int s = g_sorted[p];
        float4 v = __ldg(&x4[(size_t)s * 32 + lane]);
        acc.x += v.x; acc.y += v.y; acc.z += v.z; acc.w += v.w;
    }
    float inv = (end > beg) ? 1.0f / (float)(end - beg) : 0.0f;
    acc.x *= inv; acc.y *= inv; acc.z *= inv; acc.w *= inv;
    out4[(size_t)gw * 32 + lane] = acc;
}

// ---------------------------------------------------------------------------
// fused dual-GEMM + bias + relu: C[n][j] = relu(sum_k A0[n][k]*BT[k][j]
//                                              + sum_k A1[n][k]*BT[128+k][j] + b[j])
// 128x128 block tile, 8x8 per thread, packed f32x2 FMA (pairs along j).
__device__ __forceinline__ unsigned long long dup2(float x) {
    unsigned long long r;
    asm("mov.b64 %0, {%1, %1};" : "=l"(r) : "f"(x));
    return r;
}
__device__ __forceinline__ void fma2(unsigned long long& c, unsigned long long a,
                                     unsigned long long b) {
    asm("fma.rn.f32x2 %0, %1, %2, %0;" : "+l"(c) : "l"(a), "l"(b));
}

__global__ __launch_bounds__(256, 2) void gemm_relu_kernel(
    const float* __restrict__ A0, const float* __restrict__ A1,
    const float* __restrict__ BT, const float* __restrict__ bias,
    float* __restrict__ C, int N)
{
    __shared__ float As[8][128];
    __shared__ float Bs[8][128];
    int t = threadIdx.x;
    int ty = t >> 4, tx = t & 15;
    int r0 = ty * 8, c0 = tx * 8;
    int blockRow = blockIdx.x * 128;

    unsigned long long acc[8][4];
    #pragma unroll
    for (int r = 0; r < 8; r++)
        #pragma unroll
        for (int jp = 0; jp < 4; jp++) acc[r][jp] = 0ull;

    int rowl = t >> 1;           // A-load: row within tile
    int q = t & 1;               // which float4 of the 8-wide k chunk
    int grow = blockRow + rowl;
    bool rv = grow < N;
    const float4* A04 = (const float4*)A0;
    const float4* A14 = (const float4*)A1;
    const float4* BT4 = (const float4*)BT;
    int bkk = t >> 5, bj4 = t & 31;

    for (int kt = 0; kt < 32; kt++) {
        const float4* Asrc = (kt < 16) ? A04 : A14;
        int kq = ((kt & 15) << 1) + q;
        float4 av = rv ? __ldg(&Asrc[(size_t)grow * 32 + kq]) : make_float4(0, 0, 0, 0);
        float4 bv4 = __ldg(&BT4[(size_t)(kt * 8 + bkk) * 32 + bj4]);
        __syncthreads();
        int ks = q * 4;
        As[ks + 0][rowl] = av.x; As[ks + 1][rowl] = av.y;
        As[ks + 2][rowl] = av.z; As[ks + 3][rowl] = av.w;
        *(float4*)&Bs[bkk][bj4 * 4] = bv4;
        __syncthreads();
        #pragma unroll
        for (int kk = 0; kk < 8; kk++) {
            float4 a0 = *(const float4*)&As[kk][r0];
            float4 a1 = *(const float4*)&As[kk][r0 + 4];
            unsigned long long ad[8];
            ad[0] = dup2(a0.x); ad[1] = dup2(a0.y); ad[2] = dup2(a0.z); ad[3] = dup2(a0.w);
            ad[4] = dup2(a1.x); ad[5] = dup2(a1.y); ad[6] = dup2(a1.z); ad[7] = dup2(a1.w);
            ulonglong2 b01 = *(const ulonglong2*)&Bs[kk][c0];
            ulonglong2 b23 = *(const ulonglong2*)&Bs[kk][c0 + 4];
            unsigned long long bv[4] = {b01.x, b01.y, b23.x, b23.y};
            #pragma unroll
            for (int r = 0; r < 8; r++)
                #pragma unroll
                for (int jp = 0; jp < 4; jp++) fma2(acc[r][jp], ad[r], bv[jp]);
        }
    }

    float4 bb0 = *(const float4*)&bias[c0];
    float4 bb1 = *(const float4*)&bias[c0 + 4];
    float barr[8] = {bb0.x, bb0.y, bb0.z, bb0.w, bb1.x, bb1.y, bb1.z, bb1.w};
    #pragma unroll
    for (int r = 0; r < 8; r++) {
        int grow2 = blockRow + r0 + r;
        if (grow2 < N) {
            float o[8];
            #pragma unroll
            for (int jp = 0; jp < 4; jp++) {
                float2 f = *(float2*)&acc[r][jp];
                o[jp * 2]     = fmaxf(f.x + barr[jp * 2], 0.f);
                o[jp * 2 + 1] = fmaxf(f.y + barr[jp * 2 + 1], 0.f);
            }
            float4* cp = (float4*)&C[(size_t)grow2 * 128 + c0];
            cp[0] = make_float4(o[0], o[1], o[2], o[3]);
            cp[1] = make_float4(o[4], o[5], o[6], o[7]);
        }
    }
}

// final projection: out[n][0..3] = h2[n] . wout[j] + bout[j]; warp per node
__global__ void outproj_kernel(const float4* __restrict__ h4, const float* __restrict__ wout,
                               const float* __restrict__ bout, float4* __restrict__ out, int N) {
    int gw = (blockIdx.x * blockDim.x + threadIdx.x) >> 5;
    int lane = threadIdx.x & 31;
    if (gw >= N) return;
    float4 v = h4[(size_t)gw * 32 + lane];
    const float4* w4 = (const float4*)wout;
    float acc[4];
    #pragma unroll
    for (int j = 0; j < 4; j++) {
        float4 w = __ldg(&w4[j * 32 + lane]);
        acc[j] = v.x * w.x + v.y * w.y + v.z * w.z + v.w * w.w;
    }
    #pragma unroll
    for (int j = 0; j < 4; j++)
        #pragma unroll
        for (int o = 16; o > 0; o >>= 1) acc[j] += __shfl_down_sync(0xffffffffu, acc[j], o);
    if (lane == 0)
        out[gw] = make_float4(acc[0] + bout[0], acc[1] + bout[1],
                              acc[2] + bout[2], acc[3] + bout[3]);
}

// ---------------------------------------------------------------------------
extern "C" void kernel_launch(void* const* d_in, const int* in_sizes, int n_in,
                              void* d_out, int out_size) {
    const float* x    = (const float*)d_in[0];
    const int*   ei   = (const int*)d_in[1];
    const float* w1l  = (const float*)d_in[2];
    const float* b1l  = (const float*)d_in[3];
    const float* w1r  = (const float*)d_in[4];
    const float* w2l  = (const float*)d_in[5];
    const float* b2l  = (const float*)d_in[6];
    const float* w2r  = (const float*)d_in[7];
    const float* wout = (const float*)d_in[8];
    const float* bout = (const float*)d_in[9];
    float* out = (float*)d_out;

    int E = in_sizes[1] / 2;
    const int* src = ei;
    const int* dst = ei + E;

    float *mean, *h1, *h2, *bt1, *bt2;
    cudaGetSymbolAddress((void**)&mean, g_mean);
    cudaGetSymbolAddress((void**)&h1, g_h1);
    cudaGetSymbolAddress((void**)&h2, g_h2);
    cudaGetSymbolAddress((void**)&bt1, g_bt1);
    cudaGetSymbolAddress((void**)&bt2, g_bt2);

    // build CSR (counting sort by dst)
    zero_count_kernel<<<(NN + 255) / 256, 256>>>();
    hist_kernel<<<2048, 256>>>(dst, E);
    scan_kernel<<<1, 1024>>>();
    scatter_kernel<<<2048, 256>>>(src, dst, E);

    // pack weights into k-major concatenated form
    pack_bt_kernel<<<(256 * 128 + 255) / 256, 256>>>(w1l, w1r, bt1);
    pack_bt_kernel<<<(256 * 128 + 255) / 256, 256>>>(w2l, w2r, bt2);

    int aggBlocks = (NN * 32 + 255) / 256;        // one warp per node
    int gemmBlocks = (NN + 127) / 128;

    // layer 1
    agg_kernel<<<aggBlocks, 256>>>((const float4*)x, (float4*)mean);
    gemm_relu_kernel<<<gemmBlocks, 256>>>(mean, x, bt1, b1l, h1, NN);
    // layer 2
    agg_kernel<<<aggBlocks, 256>>>((const float4*)h1, (float4*)mean);
    gemm_relu_kernel<<<gemmBlocks, 256>>>(mean, h1, bt2, b2l, h2, NN);
    // output projection
    outproj_kernel<<<aggBlocks, 256>>>((const float4*)h2, wout, bout, (float4*)out, NN);
}

// round 7
// speedup vs baseline: 1.7964x; 1.7964x over previous
#include <cuda_runtime.h>
#include <cuda_bf16.h>
#include <cstdint>
#include <cstddef>

#define NN 100000
#define EMAX 1600000
#define TILES 782          // ceil(NN/128)

// ---- static device scratch ----
__device__ int      g_count[NN];
__device__ int      g_offsets[NN + 1];
__device__ int      g_cursor[NN];
__device__ int      g_bsum[128];
__device__ int      g_sorted[EMAX];
__device__ float    g_mean[(size_t)NN * 128];
__device__ float    g_h1[(size_t)NN * 128];
__device__ float    g_h2[(size_t)NN * 128];
__device__ uint32_t g_bp1[32768];   // fragment-order packed B (hi/lo bf16x2), 128KB
__device__ uint32_t g_bp2[32768];

// ===================== CSR build =====================
__global__ void zero_count_kernel() {
    int i = blockIdx.x * blockDim.x + threadIdx.x;
    if (i < NN) g_count[i] = 0;
}
__global__ void hist_kernel(const int* __restrict__ dst, int E) {
    for (int e = blockIdx.x * blockDim.x + threadIdx.x; e < E; e += gridDim.x * blockDim.x)
        atomicAdd(&g_count[dst[e]], 1);
}
// phase 1: per-block (1024) local exclusive scan + block sums
__global__ void scan_local_kernel() {
    __shared__ int ws[32];
    int i = blockIdx.x * 1024 + threadIdx.x;
    int lane = threadIdx.x & 31, w = threadIdx.x >> 5;
    int v = (i < NN) ? g_count[i] : 0;
    int x = v;
    #pragma unroll
    for (int o = 1; o < 32; o <<= 1) { int y = __shfl_up_sync(~0u, x, o); if (lane >= o) x += y; }
    if (lane == 31) ws[w] = x;
    __syncthreads();
    if (w == 0) {
        int s = ws[lane];
        #pragma unroll
        for (int o = 1; o < 32; o <<= 1) { int y = __shfl_up_sync(~0u, s, o); if (lane >= o) s += y; }
        ws[lane] = s;
    }
    __syncthreads();
    int excl = (w ? ws[w - 1] : 0) + x - v;
    if (i < NN) g_offsets[i] = excl;
    if (threadIdx.x == 0) g_bsum[blockIdx.x] = ws[31];
}
// phase 2: scan block sums (1 block, 128 threads)
__global__ void scan_bsum_kernel(int nseg) {
    __shared__ int sh[4];
    int t = threadIdx.x, lane = t & 31, w = t >> 5;
    int v = (t < nseg) ? g_bsum[t] : 0;
    int x = v;
    #pragma unroll
    for (int o = 1; o < 32; o <<= 1) { int y = __shfl_up_sync(~0u, x, o); if (lane >= o) x += y; }
    if (lane == 31) sh[w] = x;
    __syncthreads();
    int add = 0;
    for (int j = 0; j < w; j++) add += sh[j];
    int incl = x + add;
    g_bsum[t] = incl - v;
    if (t == 127) g_offsets[NN] = incl;
}
// phase 3: add scanned block sums
__global__ void scan_add_kernel() {
    int i = blockIdx.x * blockDim.x + threadIdx.x;
    if (i < NN) {
        int o = g_offsets[i] + g_bsum[i >> 10];
        g_offsets[i] = o;
        g_cursor[i] = o;
    }
}
__global__ void scatter_kernel(const int* __restrict__ src, const int* __restrict__ dst, int E) {
    for (int e = blockIdx.x * blockDim.x + threadIdx.x; e < E; e += gridDim.x * blockDim.x) {
        int d = dst[e];
        int pos = atomicAdd(&g_cursor[d], 1);
        g_sorted[pos] = src[e];
    }
}

// ===================== B fragment pack (FULL N=128) =====================
// Logical B[n=0..127][k=0..255]: k<128 -> Wl[n][k], else Wr[n][k-128].
// mma.sync m16n8k16 col-B fragment: lane l, nb block: reg0 = B[k=gk*16+2(l&3)+{0,1}][n],
// reg1 = same with k+8, n = nb*8 + (l>>2).
// Word index: (((gk*2 + term)*4 + nw)*2 + p)*128 + lane*4 + j
//   term: 0=hi,1=lo; nw = warp col group (n base nw*32); p pair; j: {reg0 nb=2p, reg1 nb=2p,
//   reg0 nb=2p+1, reg1 nb=2p+1} with local nb = p*2 + (j>>1).
__global__ void pack_bp_kernel(const float* __restrict__ wl, const float* __restrict__ wr,
                               uint32_t* __restrict__ bp) {
    int idx = blockIdx.x * blockDim.x + threadIdx.x;
    if (idx >= 32768) return;
    int j = idx & 3, lane = (idx >> 2) & 31, p = (idx >> 7) & 1;
    int nw = (idx >> 8) & 3, term = (idx >> 10) & 1, gk = idx >> 11;
    int nb = p * 2 + (j >> 1), reg = j & 1;
    int n = nw * 32 + nb * 8 + (lane >> 2);
    int k = gk * 16 + reg * 8 + 2 * (lane & 3);
    float v0 = (k < 128) ? wl[n * 128 + k] : wr[n * 128 + (k - 128)];
    float v1 = (k + 1 < 128) ? wl[n * 128 + k + 1] : wr[n * 128 + (k + 1 - 128)];
    __nv_bfloat162 h2 = __float22bfloat162_rn(make_float2(v0, v1));
    if (term == 0) {
        bp[idx] = *(uint32_t*)&h2;
    } else {
        float r0 = v0 - __low2float(h2);
        float r1 = v1 - __high2float(h2);
        __nv_bfloat162 l2 = __float22bfloat162_rn(make_float2(r0, r1));
        bp[idx] = *(uint32_t*)&l2;
    }
}

// ===================== aggregation (mean over in-edges) =====================
__global__ void agg_kernel(const float4* __restrict__ x4, float4* __restrict__ out4) {
    int gw = (blockIdx.x * blockDim.x + threadIdx.x) >> 5;
    int lane = threadIdx.x & 31;
    if (gw >= NN) return;
    int beg = g_offsets[gw], end = g_offsets[gw + 1];
    float4 acc = make_float4(0.f, 0.f, 0.f, 0.f);
    int p = beg;
    for (; p + 4 <= end; p += 4) {
        int s0 = g_sorted[p], s1 = g_sorted[p + 1], s2 = g_sorted[p + 2], s3 = g_sorted[p + 3];
        float4 v0 = __ldg(&x4[(size_t)s0 * 32 + lane]);
        float4 v1 = __ldg(&x4[(size_t)s1 * 32 + lane]);
        float4 v2 = __ldg(&x4[(size_t)s2 * 32 + lane]);
        float4 v3 = __ldg(&x4[(size_t)s3 * 32 + lane]);
        acc.x += (v0.x + v1.x) + (v2.x + v3.x);
        acc.y += (v0.y + v1.y) + (v2.y + v3.y);
        acc.z += (v0.z + v1.z) + (v2.z + v3.z);
        acc.w += (v0.w + v1.w) + (v2.w + v3.w);
    }
    for (; p < end; p++) {
        int s = g_sorted[p];
        float4 v = __ldg(&x4[(size_t)s * 32 + lane]);
        acc.x += v.x; acc.y += v.y; acc.z += v.z; acc.w += v.w;
    }
    float inv = (end > beg) ? 1.0f / (float)(end - beg) : 0.0f;
    acc.x *= inv; acc.y *= inv; acc.z *= inv; acc.w *= inv;
    out4[(size_t)gw * 32 + lane] = acc;
}

// ===================== mma.sync GEMM =====================
// C[n][j] = relu( sum_k A0[n][k] B[j][k] + sum_k A1[n][k] B[j][128+k] + bias[j] )
// bf16 3-term split; block tile 128x128; 8 warps = 2(M) x 4(N); warp tile 64x32.
// smem: A hi [128 x 144B], A lo [128 x 144B], bias 512B. B frags read from gmem (L1-resident).
#define AROW 144
#define SM_AHI  0
#define SM_ALO  18432
#define SM_BIAS 36864
#define GEMM_SMEM 37376

__device__ __forceinline__ uint32_t smem_u32(const void* p) {
    uint32_t a;
    asm("{ .reg .u64 t; cvta.to.shared.u64 t, %1; cvt.u32.u64 %0, t; }" : "=r"(a) : "l"(p));
    return a;
}
__device__ __forceinline__ void ldm_x4(uint32_t* r, uint32_t addr) {
    asm volatile("ldmatrix.sync.aligned.m8n8.x4.shared.b16 {%0,%1,%2,%3}, [%4];"
                 : "=r"(r[0]), "=r"(r[1]), "=r"(r[2]), "=r"(r[3]) : "r"(addr));
}
__device__ __forceinline__ void mma_bf16(float* d, const uint32_t* a, uint32_t b0, uint32_t b1) {
    asm volatile("mma.sync.aligned.m16n8k16.row.col.f32.bf16.bf16.f32 "
                 "{%0,%1,%2,%3}, {%4,%5,%6,%7}, {%8,%9}, {%0,%1,%2,%3};"
                 : "+f"(d[0]), "+f"(d[1]), "+f"(d[2]), "+f"(d[3])
                 : "r"(a[0]), "r"(a[1]), "r"(a[2]), "r"(a[3]), "r"(b0), "r"(b1));
}

__global__ __launch_bounds__(256, 2) void gemm_mma_kernel(
    const float* __restrict__ A0, const float* __restrict__ A1,
    const uint32_t* __restrict__ Bp, const float* __restrict__ bias,
    float* __restrict__ C)
{
    extern __shared__ char smem[];
    uint32_t sb = smem_u32(smem);
    int t = threadIdx.x, wid = t >> 5, lane = t & 31;
    int mw = wid >> 2, nw = wid & 3;      // warp grid 2 x 4

    if (t < 128) ((float*)(smem + SM_BIAS))[t] = bias[t];

    // per-thread fill coords: row r = t>>1, k-half h = t&1 (32 elems)
    int frow = t >> 1, fh = t & 1;
    // ldmatrix per-lane row/col offsets
    int lrow = (lane & 7) + ((lane >> 3) & 1) * 8;   // row within 16
    int lkb  = (lane >> 4) * 16;                     // +16B for k8..15 tiles
    const float* bsm = (const float*)(smem + SM_BIAS);
    // B fragment base for this warp (word units): + gk*2048 per k16-step
    const uint4* bfrag = (const uint4*)(Bp) + ((nw * 2) * 128 + lane * 4) / 4;

    for (int tile = blockIdx.x; tile < TILES; tile += gridDim.x) {
        float acc[4][4][4];
        #pragma unroll
        for (int m = 0; m < 4; m++)
            #pragma unroll
            for (int nb = 0; nb < 4; nb++)
                #pragma unroll
                for (int r = 0; r < 4; r++) acc[m][nb][r] = 0.f;

        int grow = tile * 128 + frow;
        bool rv = grow < NN;

        #pragma unroll 1
        for (int c = 0; c < 4; c++) {            // K chunks of 64
            __syncthreads();                     // prev chunk's ldmatrix done
            // ---- fill A chunk: 32 fp32 -> 16 bf16x2 hi + 16 lo ----
            {
                const float* As = (c < 2) ? A0 : A1;
                const float4* ap = (const float4*)As + (size_t)grow * 32 + ((c & 1) * 16 + fh * 8);
                float4 v[8];
                if (rv) {
                    #pragma unroll
                    for (int i = 0; i < 8; i++) v[i] = __ldg(ap + i);
                } else {
                    #pragma unroll
                    for (int i = 0; i < 8; i++) v[i] = make_float4(0.f, 0.f, 0.f, 0.f);
                }
                const float* vf = (const float*)v;
                uint32_t hw[16], lw[16];
                #pragma unroll
                for (int i = 0; i < 16; i++) {
                    float f0 = vf[2 * i], f1 = vf[2 * i + 1];
                    __nv_bfloat162 h2 = __float22bfloat162_rn(make_float2(f0, f1));
                    float r0 = f0 - __low2float(h2);
                    float r1 = f1 - __high2float(h2);
                    __nv_bfloat162 l2 = __float22bfloat162_rn(make_float2(r0, r1));
                    hw[i] = *(uint32_t*)&h2;
                    lw[i] = *(uint32_t*)&l2;
                }
                char* hb = smem + SM_AHI + frow * AROW + fh * 64;
                char* lb = smem + SM_ALO + frow * AROW + fh * 64;
                #pragma unroll
                for (int q = 0; q < 4; q++) {
                    *(uint4*)(hb + q * 16) = make_uint4(hw[4*q], hw[4*q+1], hw[4*q+2], hw[4*q+3]);
                    *(uint4*)(lb + q * 16) = make_uint4(lw[4*q], lw[4*q+1], lw[4*q+2], lw[4*q+3]);
                }
            }
            __syncthreads();
            // ---- compute: 4 k16-steps ----
            #pragma unroll
            for (int ks = 0; ks < 4; ks++) {
                int gk = c * 4 + ks;
                // B frags from gmem/L1: layout (((gk*2+term)*4+nw)*2+p)*128 + lane*4, 16B each
                const uint4* bgk = bfrag + (size_t)gk * 512;   // gk*2048 words /4
                uint4 bh0 = __ldg(bgk + 0);                    // term0 p0
                uint4 bh1 = __ldg(bgk + 32);                   // term0 p1 (+128 words)
                uint4 bl0 = __ldg(bgk + 256);                  // term1 p0 (+1024 words)
                uint4 bl1 = __ldg(bgk + 288);                  // term1 p1
                uint32_t bh[4][2] = {{bh0.x, bh0.y}, {bh0.z, bh0.w}, {bh1.x, bh1.y}, {bh1.z, bh1.w}};
                uint32_t bl[4][2] = {{bl0.x, bl0.y}, {bl0.z, bl0.w}, {bl1.x, bl1.y}, {bl1.z, bl1.w}};
                #pragma unroll
                for (int m = 0; m < 4; m++) {
                    uint32_t ah[4], al[4];
                    uint32_t rbase = sb + (uint32_t)((mw * 64 + m * 16 + lrow) * AROW + ks * 32 + lkb);
                    ldm_x4(ah, rbase + SM_AHI);
                    ldm_x4(al, rbase + SM_ALO);
                    #pragma unroll
                    for (int nb = 0; nb < 4; nb++) {
                        mma_bf16(acc[m][nb], ah, bh[nb][0], bh[nb][1]);
                        mma_bf16(acc[m][nb], al, bh[nb][0], bh[nb][1]);
                        mma_bf16(acc[m][nb], ah, bl[nb][0], bl[nb][1]);
                    }
                }
            }
        }
        // ---- epilogue: bias + relu + store ----
        #pragma unroll
        for (int m = 0; m < 4; m++) {
            int orow0 = tile * 128 + mw * 64 + m * 16 + (lane >> 2);
            #pragma unroll
            for (int nb = 0; nb < 4; nb++) {
                int ocol = nw * 32 + nb * 8 + 2 * (lane & 3);
                float b0 = bsm[ocol], b1 = bsm[ocol + 1];
                if (orow0 < NN) {
                    float2 o = make_float2(fmaxf(acc[m][nb][0] + b0, 0.f),
                                           fmaxf(acc[m][nb][1] + b1, 0.f));
                    *(float2*)&C[(size_t)orow0 * 128 + ocol] = o;
                }
                if (orow0 + 8 < NN) {
                    float2 o = make_float2(fmaxf(acc[m][nb][2] + b0, 0.f),
                                           fmaxf(acc[m][nb][3] + b1, 0.f));
                    *(float2*)&C[(size_t)(orow0 + 8) * 128 + ocol] = o;
                }
            }
        }
    }
}

// ===================== output projection =====================
__global__ void outproj_kernel(const float4* __restrict__ h4, const float* __restrict__ wout,
                               const float* __restrict__ bout, float4* __restrict__ out, int N) {
    int gw = (blockIdx.x * blockDim.x + threadIdx.x) >> 5;
    int lane = threadIdx.x & 31;
    if (gw >= N) return;
    float4 v = h4[(size_t)gw * 32 + lane];
    const float4* w4 = (const float4*)wout;
    float acc[4];
    #pragma unroll
    for (int j = 0; j < 4; j++) {
        float4 w = __ldg(&w4[j * 32 + lane]);
        acc[j] = v.x * w.x + v.y * w.y + v.z * w.z + v.w * w.w;
    }
    #pragma unroll
    for (int j = 0; j < 4; j++)
        #pragma unroll
        for (int o = 16; o > 0; o >>= 1) acc[j] += __shfl_down_sync(~0u, acc[j], o);
    if (lane == 0)
        out[gw] = make_float4(acc[0] + bout[0], acc[1] + bout[1],
                              acc[2] + bout[2], acc[3] + bout[3]);
}

// ===================== launch =====================
extern "C" void kernel_launch(void* const* d_in, const int* in_sizes, int n_in,
                              void* d_out, int out_size) {
    const float* x    = (const float*)d_in[0];
    const int*   ei   = (const int*)d_in[1];
    const float* w1l  = (const float*)d_in[2];
    const float* b1l  = (const float*)d_in[3];
    const float* w1r  = (const float*)d_in[4];
    const float* w2l  = (const float*)d_in[5];
    const float* b2l  = (const float*)d_in[6];
    const float* w2r  = (const float*)d_in[7];
    const float* wout = (const float*)d_in[8];
    const float* bout = (const float*)d_in[9];
    float* out = (float*)d_out;

    int E = in_sizes[1] / 2;
    const int* src = ei;
    const int* dst = ei + E;

    float *mean, *h1, *h2;
    uint32_t *bp1, *bp2;
    cudaGetSymbolAddress((void**)&mean, g_mean);
    cudaGetSymbolAddress((void**)&h1, g_h1);
    cudaGetSymbolAddress((void**)&h2, g_h2);
    cudaGetSymbolAddress((void**)&bp1, g_bp1);
    cudaGetSymbolAddress((void**)&bp2, g_bp2);

    cudaFuncSetAttribute(gemm_mma_kernel, cudaFuncAttributeMaxDynamicSharedMemorySize, GEMM_SMEM);

    // CSR build (counting sort by dst)
    zero_count_kernel<<<(NN + 255) / 256, 256>>>();
    hist_kernel<<<2048, 256>>>(dst, E);
    int nseg = (NN + 1023) / 1024;   // 98
    scan_local_kernel<<<nseg, 1024>>>();
    scan_bsum_kernel<<<1, 128>>>(nseg);
    scan_add_kernel<<<(NN + 255) / 256, 256>>>();
    scatter_kernel<<<2048, 256>>>(src, dst, E);

    // fragment-order bf16-split weight images (full N)
    pack_bp_kernel<<<128, 256>>>(w1l, w1r, bp1);
    pack_bp_kernel<<<128, 256>>>(w2l, w2r, bp2);

    int aggBlocks = (NN * 32 + 255) / 256;

    // layer 1
    agg_kernel<<<aggBlocks, 256>>>((const float4*)x, (float4*)mean);
    gemm_mma_kernel<<<296, 256, GEMM_SMEM>>>(mean, x, bp1, b1l, h1);
    // layer 2
    agg_kernel<<<aggBlocks, 256>>>((const float4*)h1, (float4*)mean);
    gemm_mma_kernel<<<296, 256, GEMM_SMEM>>>(mean, h1, bp2, b2l, h2);
    // output projection
    outproj_kernel<<<aggBlocks, 256>>>((const float4*)h2, wout, bout, (float4*)out, NN);
}